// round 6
// baseline (speedup 1.0000x reference)
#include <cuda_runtime.h>
#include <cuda_bf16.h>
#include <math.h>

// ---------------------------------------------------------------------------
// Problem constants
// ---------------------------------------------------------------------------
#define NUM_CLS 80
#define CCH     256
#define NROIS   256
#define KFEAT   12544   // 256 * 49
#define H1DIM   1024

// scratch (device globals; no allocation)
__device__ float g_T0[65536 * 256];   // P0 transposed HWC
__device__ float g_T1[16384 * 256];
__device__ float g_T2[4096 * 256];
__device__ float g_T3[1024 * 256];
__device__ float g_pool[NROIS * KFEAT];        // [n][bin*256 + c]
__device__ float g_part[8 * NROIS * 1024];     // split-K partials (reused)
__device__ float g_h1[NROIS * H1DIM];
__device__ float g_h2[NROIS * H1DIM];
__device__ float g_cls[NROIS * 81];
__device__ float g_loc[NROIS * 324];
__device__ float g_roi[NROIS * 4];
__device__ float g_valid[NROIS];
__device__ float g_preb[NROIS * NUM_CLS * 4];
__device__ float g_pres[NROIS * NUM_CLS];

__constant__ float4 c_stds[3] = {
    {0.1f, 0.1f, 0.2f, 0.2f},
    {0.05f, 0.05f, 0.1f, 0.1f},
    {1.0f / 30.0f, 1.0f / 30.0f, 1.0f / 15.0f, 1.0f / 15.0f}
};

// ---------------------------------------------------------------------------
// f32x2 packed FMA helpers (sm_103a)
// ---------------------------------------------------------------------------
__device__ __forceinline__ unsigned long long dup_f(float x) {
    unsigned long long r;
    asm("mov.b64 %0, {%1, %1};" : "=l"(r) : "f"(x));
    return r;
}
__device__ __forceinline__ void fma2(unsigned long long& d, unsigned long long a,
                                     unsigned long long b) {
    asm("fma.rn.f32x2 %0, %1, %2, %0;" : "+l"(d) : "l"(a), "l"(b));
}
__device__ __forceinline__ float2 unpack2(unsigned long long v) {
    float2 r;
    asm("mov.b64 {%0, %1}, %2;" : "=f"(r.x), "=f"(r.y) : "l"(v));
    return r;
}

// ---------------------------------------------------------------------------
// Transpose [C][HW] -> [HW][C]  (channels-last features for ROIAlign gathers)
// ---------------------------------------------------------------------------
__global__ void transpose_kernel(const float* __restrict__ src, int lvl, int HW) {
    float* dsts[4] = {g_T0, g_T1, g_T2, g_T3};
    float* dst = dsts[lvl];
    __shared__ float tile[32][33];
    int pBase = blockIdx.x * 32;
    int cBase = blockIdx.y * 32;
    int tx = threadIdx.x, ty = threadIdx.y;  // (32, 8)
#pragma unroll
    for (int r = 0; r < 4; r++)
        tile[ty + 8 * r][tx] = src[(size_t)(cBase + ty + 8 * r) * HW + pBase + tx];
    __syncthreads();
#pragma unroll
    for (int r = 0; r < 4; r++)
        dst[(size_t)(pBase + ty + 8 * r) * 256 + cBase + tx] = tile[tx][ty + 8 * r];
}

// ---------------------------------------------------------------------------
// Init accumulators / roi state
// ---------------------------------------------------------------------------
__global__ void init_state(const float* __restrict__ rois) {
    int idx = blockIdx.x * 256 + threadIdx.x;   // grid covers 81920
    if (idx < NROIS * NUM_CLS * 4) g_preb[idx] = 0.0f;
    if (idx < NROIS * NUM_CLS)     g_pres[idx] = 0.0f;
    if (idx < NROIS * 4)           g_roi[idx] = rois[idx];
    if (idx < NROIS)               g_valid[idx] = 1.0f;
}

// ---------------------------------------------------------------------------
// ROIAlign (out=7, SR=2) on channels-last features.
// One block per roi; 256 threads; thread owns 4 channels (float4).
// Output layout: g_pool[n][bin*256 + c]  (coalesced stores).
// ---------------------------------------------------------------------------
__global__ void roialign_kernel() {
    const int n = blockIdx.x;
    const int tid = threadIdx.x;

    __shared__ int   s_iy0[14], s_iy1[14], s_ix0[14], s_ix1[14];
    __shared__ float s_ly[14], s_lx[14];
    __shared__ int   s_vy[14], s_vx[14];
    __shared__ int   s_lvl;

    const float r0 = g_roi[n * 4 + 0];
    const float r1 = g_roi[n * 4 + 1];
    const float r2 = g_roi[n * 4 + 2];
    const float r3 = g_roi[n * 4 + 3];

    if (tid == 0) {
        float area = (r2 - r0 + 1.0f) * (r3 - r1 + 1.0f);
        float lv = floorf(4.0f + log2f(sqrtf(area) / 224.0f));
        lv = fminf(fmaxf(lv, 2.0f), 5.0f) - 2.0f;
        s_lvl = (int)lv;
    }
    __syncthreads();

    const int l = s_lvl;
    const int Hdims[4] = {256, 128, 64, 32};
    const float scales[4] = {0.25f, 0.125f, 0.0625f, 0.03125f};
    const int H = Hdims[l];
    const int W = H;
    const float scale = scales[l];

    if (tid < 28) {
        bool isx = tid >= 14;
        int t = isx ? tid - 14 : tid;
        float a  = isx ? r1 : r0;
        float b2 = isx ? r3 : r2;
        float lo = a * scale;
        float len = fmaxf(b2 * scale - lo, 1.0f);
        float g = (float)(t >> 1) + ((float)(t & 1) + 0.5f) * 0.5f;
        float coord = lo + g * (len / 7.0f);
        int v = (coord > -1.0f) && (coord < (float)H);
        float cc = fminf(fmaxf(coord, 0.0f), (float)H - 1.0f);
        float f0 = floorf(cc);
        int i0 = (int)f0;
        int i1 = min(i0 + 1, H - 1);
        float fr = cc - f0;
        if (isx) { s_vx[t] = v; s_ix0[t] = i0; s_ix1[t] = i1; s_lx[t] = fr; }
        else     { s_vy[t] = v; s_iy0[t] = i0; s_iy1[t] = i1; s_ly[t] = fr; }
    }
    __syncthreads();

    const float* Ts[4] = {g_T0, g_T1, g_T2, g_T3};
    const float4* F = (const float4*)Ts[l];

    const int c4 = tid & 63;    // channel group (4 channels)
    const int grp = tid >> 6;   // 4 bin groups
    float4* outp = (float4*)(g_pool + (size_t)n * KFEAT);

    for (int bin = grp; bin < 49; bin += 4) {
        int oy = bin / 7;
        int ox = bin - oy * 7;
        float4 acc = {0.f, 0.f, 0.f, 0.f};
#pragma unroll
        for (int jy = 0; jy < 2; jy++) {
            int sy = oy * 2 + jy;
            int vy = s_vy[sy];
            float ly = s_ly[sy];
            int y0 = s_iy0[sy], y1i = s_iy1[sy];
#pragma unroll
            for (int jx = 0; jx < 2; jx++) {
                int sx = ox * 2 + jx;
                if (vy && s_vx[sx]) {
                    float lx = s_lx[sx];
                    int x0 = s_ix0[sx], x1i = s_ix1[sx];
                    float4 f00 = F[(size_t)(y0 * W + x0) * 64 + c4];
                    float4 f01 = F[(size_t)(y0 * W + x1i) * 64 + c4];
                    float4 f10 = F[(size_t)(y1i * W + x0) * 64 + c4];
                    float4 f11 = F[(size_t)(y1i * W + x1i) * 64 + c4];
                    float w00 = (1.f - ly) * (1.f - lx);
                    float w01 = (1.f - ly) * lx;
                    float w10 = ly * (1.f - lx);
                    float w11 = ly * lx;
                    acc.x += f00.x * w00 + f01.x * w01 + f10.x * w10 + f11.x * w11;
                    acc.y += f00.y * w00 + f01.y * w01 + f10.y * w10 + f11.y * w11;
                    acc.z += f00.z * w00 + f01.z * w01 + f10.z * w10 + f11.z * w11;
                    acc.w += f00.w * w00 + f01.w * w01 + f10.w * w10 + f11.w * w11;
                }
            }
        }
        acc.x *= 0.25f; acc.y *= 0.25f; acc.z *= 0.25f; acc.w *= 0.25f;
        outp[bin * 64 + c4] = acc;
    }
}

// ---------------------------------------------------------------------------
// Split-K GEMM, fp32 with packed f32x2 FMA.
// C[M=256, N] = A[256, Ktot] * B[Ktot, N] into per-split partials.
// PERM: B row index remap k -> (k%256)*49 + (k/256) (pool layout -> W1 rows).
// ---------------------------------------------------------------------------
#define BM 64
#define BN 64
#define TK 16

template <bool PERM>
__global__ __launch_bounds__(256) void gemm_splitk(
    const float* __restrict__ B, int Asel, int N, int Ktot, int Kc, int partOff) {
    const float* Asrcs[3] = {g_pool, g_h1, g_h2};
    const float* A = Asrcs[Asel];

    __shared__ float As[TK][BM + 4];
    __shared__ float Bs[TK][BN + 4];

    const int tid = threadIdx.x;
    const int split = blockIdx.z;
    const int mBase = blockIdx.y * BM;
    const int nBase = blockIdx.x * BN;
    const int k0 = split * Kc;

    const int am = tid >> 2;          // A row within tile
    const int ak = (tid & 3) * 4;     // A k-offset
    const int bk = tid >> 4;          // B row within k-tile
    const int bj = (tid & 15) * 4;    // B col offset
    const int tx = tid & 15;
    const int ty = tid >> 4;

    unsigned long long acc[2][4];
#pragma unroll
    for (int p = 0; p < 2; p++)
#pragma unroll
        for (int q = 0; q < 4; q++) acc[p][q] = 0ull;

    const bool nfull = ((nBase + BN) <= N) && ((N & 3) == 0);
    const float* Arow = A + (size_t)(mBase + am) * Ktot + k0 + ak;
    const int ntiles = Kc / TK;

    for (int t = 0; t < ntiles; t++) {
        // load A tile (transposed into shared)
        float4 av = *(const float4*)(Arow + t * TK);
        As[ak + 0][am] = av.x;
        As[ak + 1][am] = av.y;
        As[ak + 2][am] = av.z;
        As[ak + 3][am] = av.w;
        // load B tile
        int kk = k0 + t * TK + bk;
        int krow = PERM ? ((kk & 255) * 49 + (kk >> 8)) : kk;
        const float* Bp = B + (size_t)krow * N + nBase + bj;
        float4 bv;
        if (nfull) {
            bv = *(const float4*)Bp;
        } else {
            bv.x = (nBase + bj + 0 < N) ? Bp[0] : 0.0f;
            bv.y = (nBase + bj + 1 < N) ? Bp[1] : 0.0f;
            bv.z = (nBase + bj + 2 < N) ? Bp[2] : 0.0f;
            bv.w = (nBase + bj + 3 < N) ? Bp[3] : 0.0f;
        }
        *(float4*)&Bs[bk][bj] = bv;
        __syncthreads();

#pragma unroll
        for (int kx = 0; kx < TK; kx++) {
            ulonglong2 ap = *(const ulonglong2*)&As[kx][ty * 4];
            float4 bq = *(const float4*)&Bs[kx][tx * 4];
            unsigned long long b0 = dup_f(bq.x);
            unsigned long long b1 = dup_f(bq.y);
            unsigned long long b2 = dup_f(bq.z);
            unsigned long long b3 = dup_f(bq.w);
            fma2(acc[0][0], ap.x, b0);
            fma2(acc[0][1], ap.x, b1);
            fma2(acc[0][2], ap.x, b2);
            fma2(acc[0][3], ap.x, b3);
            fma2(acc[1][0], ap.y, b0);
            fma2(acc[1][1], ap.y, b1);
            fma2(acc[1][2], ap.y, b2);
            fma2(acc[1][3], ap.y, b3);
        }
        __syncthreads();
    }

    float* P = g_part + partOff + (size_t)split * NROIS * N;
#pragma unroll
    for (int p = 0; p < 2; p++) {
        int m = mBase + ty * 4 + p * 2;
#pragma unroll
        for (int q = 0; q < 4; q++) {
            float2 v = unpack2(acc[p][q]);
            int col = nBase + tx * 4 + q;
            if (col < N) {
                P[(size_t)m * N + col] = v.x;
                P[(size_t)(m + 1) * N + col] = v.y;
            }
        }
    }
}

// fixed-order split reduction + bias (+ optional relu)
__global__ void reduce_bias(const float* __restrict__ bias, int outSel, int N,
                            int splits, int relu, int partOff) {
    float* outs[4] = {g_h1, g_h2, g_cls, g_loc};
    float* out = outs[outSel];
    int idx = blockIdx.x * 256 + threadIdx.x;
    int MN = NROIS * N;
    if (idx >= MN) return;
    const float* P = g_part + partOff;
    float s = 0.0f;
    for (int sp = 0; sp < splits; sp++) s += P[(size_t)sp * MN + idx];
    s += bias[idx % N];
    if (relu) s = fmaxf(s, 0.0f);
    out[idx] = s;
}

// ---------------------------------------------------------------------------
// Per-roi postprocess: softmax, box decode, accumulate, argmax, roi update.
// ---------------------------------------------------------------------------
__global__ void postproc(int stage) {
    const int n = blockIdx.x;
    const int tid = threadIdx.x;   // 128 threads

    __shared__ float sl[81];
    __shared__ float ssc[80];
    __shared__ float sbox[80][4];
    __shared__ float sred[128];
    __shared__ int sidx[128];

    if (tid < 81) sl[tid] = g_cls[n * 81 + tid];
    __syncthreads();

    // max
    float m = -1e30f;
    if (tid < 81) m = sl[tid];
    sred[tid] = m;
    __syncthreads();
    for (int off = 64; off > 0; off >>= 1) {
        if (tid < off) sred[tid] = fmaxf(sred[tid], sred[tid + off]);
        __syncthreads();
    }
    const float M = sred[0];
    __syncthreads();

    // exp-sum
    float e = (tid < 81) ? expf(sl[tid] - M) : 0.0f;
    sred[tid] = e;
    __syncthreads();
    for (int off = 64; off > 0; off >>= 1) {
        if (tid < off) sred[tid] += sred[tid + off];
        __syncthreads();
    }
    const float S = sred[0];
    __syncthreads();
    if (tid >= 1 && tid < 81) ssc[tid - 1] = e / S;
    __syncthreads();

    const float r0 = g_roi[n * 4 + 0];
    const float r1 = g_roi[n * 4 + 1];
    const float r2 = g_roi[n * 4 + 2];
    const float r3 = g_roi[n * 4 + 3];
    const float chy = r2 - r0, chx = r3 - r1;
    const float cy = r0 + chy * 0.5f, cx = r1 + chx * 0.5f;
    const float4 stds = c_stds[stage];

    if (tid < 80) {
        const int j = tid;
        g_pres[n * 80 + j] += ssc[j];
        const float* lp = g_loc + n * 324 + (j + 1) * 4;
        float l0 = lp[0] * stds.x;
        float l1 = lp[1] * stds.y;
        float l2 = lp[2] * stds.z;
        float l3 = lp[3] * stds.w;
        float ty_ = l0 * chy + cy;
        float tx_ = l1 * chx + cx;
        float hy = expf(l2) * chy;
        float hx = expf(l3) * chx;
        float b0 = ty_ - hy * 0.5f;
        float b1 = tx_ - hx * 0.5f;
        float b2 = ty_ + hy * 0.5f;
        float b3 = tx_ + hx * 0.5f;
        sbox[j][0] = b0; sbox[j][1] = b1; sbox[j][2] = b2; sbox[j][3] = b3;
        float* pb = g_preb + (size_t)(n * 80 + j) * 4;
        pb[0] += b0; pb[1] += b1; pb[2] += b2; pb[3] += b3;
    }

    // argmax (first occurrence on ties)
    sred[tid] = (tid < 80) ? ssc[tid] : -1e30f;
    sidx[tid] = (tid < 80) ? tid : (1 << 30);
    __syncthreads();
    for (int off = 64; off > 0; off >>= 1) {
        if (tid < off) {
            float v2 = sred[tid + off];
            int i2 = sidx[tid + off];
            if (v2 > sred[tid] || (v2 == sred[tid] && i2 < sidx[tid])) {
                sred[tid] = v2;
                sidx[tid] = i2;
            }
        }
        __syncthreads();
    }
    if (tid == 0) {
        int best = sidx[0];
        float nr0 = fminf(fmaxf(sbox[best][0], 0.0f), 1024.0f);
        float nr1 = fminf(fmaxf(sbox[best][1], 0.0f), 1024.0f);
        float nr2 = fminf(fmaxf(sbox[best][2], 0.0f), 1024.0f);
        float nr3 = fminf(fmaxf(sbox[best][3], 0.0f), 1024.0f);
        g_roi[n * 4 + 0] = nr0;
        g_roi[n * 4 + 1] = nr1;
        g_roi[n * 4 + 2] = nr2;
        g_roi[n * 4 + 3] = nr3;
        if (stage < 2) {
            float hy = nr2 - nr0, hx = nr3 - nr1;
            if (!(hy >= 16.0f && hx >= 16.0f)) g_valid[n] = 0.0f;
        }
    }
}

// final: d_out = [pre_b/3*m (81920) | pre_s/3*m (20480)]
__global__ void finalize_kernel(float* __restrict__ out) {
    int idx = blockIdx.x * 256 + threadIdx.x;   // grid covers 81920
    if (idx < NROIS * NUM_CLS * 4) {
        int n = idx / (NUM_CLS * 4);
        out[idx] = g_preb[idx] * (1.0f / 3.0f) * g_valid[n];
    }
    if (idx < NROIS * NUM_CLS) {
        int n = idx / NUM_CLS;
        out[NROIS * NUM_CLS * 4 + idx] = g_pres[idx] * (1.0f / 3.0f) * g_valid[n];
    }
}

// ---------------------------------------------------------------------------
// launch
// ---------------------------------------------------------------------------
extern "C" void kernel_launch(void* const* d_in, const int* in_sizes, int n_in,
                              void* d_out, int out_size) {
    (void)in_sizes; (void)n_in; (void)out_size;
    const float* P0 = (const float*)d_in[0];
    const float* P1 = (const float*)d_in[1];
    const float* P2 = (const float*)d_in[2];
    const float* P3 = (const float*)d_in[3];
    const float* rois = (const float*)d_in[4];

    dim3 tb(32, 8);
    transpose_kernel<<<dim3(65536 / 32, 8), tb>>>(P0, 0, 65536);
    transpose_kernel<<<dim3(16384 / 32, 8), tb>>>(P1, 1, 16384);
    transpose_kernel<<<dim3(4096 / 32, 8), tb>>>(P2, 2, 4096);
    transpose_kernel<<<dim3(1024 / 32, 8), tb>>>(P3, 3, 1024);

    init_state<<<320, 256>>>(rois);

    const int LOC_PART_OFF = 4 * NROIS * 81;  // 82944 floats into g_part

    for (int s = 0; s < 3; s++) {
        const float* W1 = (const float*)d_in[5 + 8 * s + 0];
        const float* b1 = (const float*)d_in[5 + 8 * s + 1];
        const float* W2 = (const float*)d_in[5 + 8 * s + 2];
        const float* b2 = (const float*)d_in[5 + 8 * s + 3];
        const float* Wc = (const float*)d_in[5 + 8 * s + 4];
        const float* bc = (const float*)d_in[5 + 8 * s + 5];
        const float* Wl = (const float*)d_in[5 + 8 * s + 6];
        const float* bl = (const float*)d_in[5 + 8 * s + 7];

        roialign_kernel<<<NROIS, 256>>>();

        // FC1: [256,12544] x [12544,1024], split-K=8
        gemm_splitk<true><<<dim3(16, 4, 8), 256>>>(W1, 0, 1024, 12544, 1568, 0);
        reduce_bias<<<1024, 256>>>(b1, 0, 1024, 8, 1, 0);

        // FC2: [256,1024] x [1024,1024], split-K=4
        gemm_splitk<false><<<dim3(16, 4, 4), 256>>>(W2, 1, 1024, 1024, 256, 0);
        reduce_bias<<<1024, 256>>>(b2, 1, 1024, 4, 1, 0);

        // heads
        gemm_splitk<false><<<dim3(2, 4, 4), 256>>>(Wc, 2, 81, 1024, 256, 0);
        gemm_splitk<false><<<dim3(6, 4, 4), 256>>>(Wl, 2, 324, 1024, 256, LOC_PART_OFF);
        reduce_bias<<<81, 256>>>(bc, 2, 81, 4, 0, 0);
        reduce_bias<<<324, 256>>>(bl, 3, 324, 4, 0, LOC_PART_OFF);

        postproc<<<NROIS, 128>>>(s);
    }

    finalize_kernel<<<320, 256>>>((float*)d_out);
}

// round 7
// speedup vs baseline: 1.0058x; 1.0058x over previous
#include <cuda_runtime.h>
#include <cuda_bf16.h>
#include <math.h>

// ---------------------------------------------------------------------------
// Problem constants
// ---------------------------------------------------------------------------
#define NUM_CLS 80
#define CCH     256
#define NROIS   256
#define KFEAT   12544   // 256 * 49
#define H1DIM   1024

// scratch (device globals; no allocation)
__device__ float g_T0[65536 * 256];   // P0 transposed HWC
__device__ float g_T1[16384 * 256];
__device__ float g_T2[4096 * 256];
__device__ float g_T3[1024 * 256];
__device__ float g_pool[NROIS * KFEAT];        // [n][bin*256 + c]
__device__ float g_part[8 * NROIS * 1024];     // split-K partials (reused)
__device__ float g_h1[NROIS * H1DIM];
__device__ float g_h2[NROIS * H1DIM];
__device__ float g_cls[NROIS * 81];
__device__ float g_loc[NROIS * 324];
__device__ float g_roi[NROIS * 4];
__device__ float g_valid[NROIS];
__device__ float g_preb[NROIS * NUM_CLS * 4];
__device__ float g_pres[NROIS * NUM_CLS];

__constant__ float4 c_stds[3] = {
    {0.1f, 0.1f, 0.2f, 0.2f},
    {0.05f, 0.05f, 0.1f, 0.1f},
    {1.0f / 30.0f, 1.0f / 30.0f, 1.0f / 15.0f, 1.0f / 15.0f}
};

// ---------------------------------------------------------------------------
// f32x2 packed FMA helpers (sm_103a)
// ---------------------------------------------------------------------------
__device__ __forceinline__ unsigned long long dup_f(float x) {
    unsigned long long r;
    asm("mov.b64 %0, {%1, %1};" : "=l"(r) : "f"(x));
    return r;
}
__device__ __forceinline__ void fma2(unsigned long long& d, unsigned long long a,
                                     unsigned long long b) {
    asm("fma.rn.f32x2 %0, %1, %2, %0;" : "+l"(d) : "l"(a), "l"(b));
}
__device__ __forceinline__ float2 unpack2(unsigned long long v) {
    float2 r;
    asm("mov.b64 {%0, %1}, %2;" : "=f"(r.x), "=f"(r.y) : "l"(v));
    return r;
}

// ---------------------------------------------------------------------------
// Transpose [C][HW] -> [HW][C]  (channels-last features for ROIAlign gathers)
// ---------------------------------------------------------------------------
__global__ void transpose_kernel(const float* __restrict__ src, int lvl, int HW) {
    float* dsts[4] = {g_T0, g_T1, g_T2, g_T3};
    float* dst = dsts[lvl];
    __shared__ float tile[32][33];
    int pBase = blockIdx.x * 32;
    int cBase = blockIdx.y * 32;
    int tx = threadIdx.x, ty = threadIdx.y;  // (32, 8)
#pragma unroll
    for (int r = 0; r < 4; r++)
        tile[ty + 8 * r][tx] = src[(size_t)(cBase + ty + 8 * r) * HW + pBase + tx];
    __syncthreads();
#pragma unroll
    for (int r = 0; r < 4; r++)
        dst[(size_t)(pBase + ty + 8 * r) * 256 + cBase + tx] = tile[tx][ty + 8 * r];
}

// ---------------------------------------------------------------------------
// Init accumulators / roi state
// ---------------------------------------------------------------------------
__global__ void init_state(const float* __restrict__ rois) {
    int idx = blockIdx.x * 256 + threadIdx.x;   // grid covers 81920
    if (idx < NROIS * NUM_CLS * 4) g_preb[idx] = 0.0f;
    if (idx < NROIS * NUM_CLS)     g_pres[idx] = 0.0f;
    if (idx < NROIS * 4)           g_roi[idx] = rois[idx];
    if (idx < NROIS)               g_valid[idx] = 1.0f;
}

// ---------------------------------------------------------------------------
// ROIAlign (out=7, SR=2) on channels-last features.
// One block per roi; 256 threads; thread owns 4 channels (float4).
// Output layout: g_pool[n][bin*256 + c]  (coalesced stores).
// ---------------------------------------------------------------------------
__global__ void roialign_kernel() {
    const int n = blockIdx.x;
    const int tid = threadIdx.x;

    __shared__ int   s_iy0[14], s_iy1[14], s_ix0[14], s_ix1[14];
    __shared__ float s_ly[14], s_lx[14];
    __shared__ int   s_vy[14], s_vx[14];
    __shared__ int   s_lvl;

    const float r0 = g_roi[n * 4 + 0];
    const float r1 = g_roi[n * 4 + 1];
    const float r2 = g_roi[n * 4 + 2];
    const float r3 = g_roi[n * 4 + 3];

    if (tid == 0) {
        float area = (r2 - r0 + 1.0f) * (r3 - r1 + 1.0f);
        float lv = floorf(4.0f + log2f(sqrtf(area) / 224.0f));
        lv = fminf(fmaxf(lv, 2.0f), 5.0f) - 2.0f;
        s_lvl = (int)lv;
    }
    __syncthreads();

    const int l = s_lvl;
    const int Hdims[4] = {256, 128, 64, 32};
    const float scales[4] = {0.25f, 0.125f, 0.0625f, 0.03125f};
    const int H = Hdims[l];
    const int W = H;
    const float scale = scales[l];

    if (tid < 28) {
        bool isx = tid >= 14;
        int t = isx ? tid - 14 : tid;
        float a  = isx ? r1 : r0;
        float b2 = isx ? r3 : r2;
        float lo = a * scale;
        float len = fmaxf(b2 * scale - lo, 1.0f);
        float g = (float)(t >> 1) + ((float)(t & 1) + 0.5f) * 0.5f;
        float coord = lo + g * (len / 7.0f);
        int v = (coord > -1.0f) && (coord < (float)H);
        float cc = fminf(fmaxf(coord, 0.0f), (float)H - 1.0f);
        float f0 = floorf(cc);
        int i0 = (int)f0;
        int i1 = min(i0 + 1, H - 1);
        float fr = cc - f0;
        if (isx) { s_vx[t] = v; s_ix0[t] = i0; s_ix1[t] = i1; s_lx[t] = fr; }
        else     { s_vy[t] = v; s_iy0[t] = i0; s_iy1[t] = i1; s_ly[t] = fr; }
    }
    __syncthreads();

    const float* Ts[4] = {g_T0, g_T1, g_T2, g_T3};
    const float4* F = (const float4*)Ts[l];

    const int c4 = tid & 63;    // channel group (4 channels)
    const int grp = tid >> 6;   // 4 bin groups
    float4* outp = (float4*)(g_pool + (size_t)n * KFEAT);

    for (int bin = grp; bin < 49; bin += 4) {
        int oy = bin / 7;
        int ox = bin - oy * 7;
        float4 acc = {0.f, 0.f, 0.f, 0.f};
#pragma unroll
        for (int jy = 0; jy < 2; jy++) {
            int sy = oy * 2 + jy;
            int vy = s_vy[sy];
            float ly = s_ly[sy];
            int y0 = s_iy0[sy], y1i = s_iy1[sy];
#pragma unroll
            for (int jx = 0; jx < 2; jx++) {
                int sx = ox * 2 + jx;
                if (vy && s_vx[sx]) {
                    float lx = s_lx[sx];
                    int x0 = s_ix0[sx], x1i = s_ix1[sx];
                    float4 f00 = F[(size_t)(y0 * W + x0) * 64 + c4];
                    float4 f01 = F[(size_t)(y0 * W + x1i) * 64 + c4];
                    float4 f10 = F[(size_t)(y1i * W + x0) * 64 + c4];
                    float4 f11 = F[(size_t)(y1i * W + x1i) * 64 + c4];
                    float w00 = (1.f - ly) * (1.f - lx);
                    float w01 = (1.f - ly) * lx;
                    float w10 = ly * (1.f - lx);
                    float w11 = ly * lx;
                    acc.x += f00.x * w00 + f01.x * w01 + f10.x * w10 + f11.x * w11;
                    acc.y += f00.y * w00 + f01.y * w01 + f10.y * w10 + f11.y * w11;
                    acc.z += f00.z * w00 + f01.z * w01 + f10.z * w10 + f11.z * w11;
                    acc.w += f00.w * w00 + f01.w * w01 + f10.w * w10 + f11.w * w11;
                }
            }
        }
        acc.x *= 0.25f; acc.y *= 0.25f; acc.z *= 0.25f; acc.w *= 0.25f;
        outp[bin * 64 + c4] = acc;
    }
}

// ---------------------------------------------------------------------------
// Split-K GEMM, fp32 with packed f32x2 FMA.
// C[M=256, N] = A[256, Ktot] * B[Ktot, N] into per-split partials.
// PERM: B row index remap k -> (k%256)*49 + (k/256) (pool layout -> W1 rows).
// ---------------------------------------------------------------------------
#define BM 64
#define BN 64
#define TK 16

template <bool PERM>
__global__ __launch_bounds__(256) void gemm_splitk(
    const float* __restrict__ B, int Asel, int N, int Ktot, int Kc, int partOff) {
    const float* Asrcs[3] = {g_pool, g_h1, g_h2};
    const float* A = Asrcs[Asel];

    __shared__ float As[TK][BM + 4];
    __shared__ float Bs[TK][BN + 4];

    const int tid = threadIdx.x;
    const int split = blockIdx.z;
    const int mBase = blockIdx.y * BM;
    const int nBase = blockIdx.x * BN;
    const int k0 = split * Kc;

    const int am = tid >> 2;          // A row within tile
    const int ak = (tid & 3) * 4;     // A k-offset
    const int bk = tid >> 4;          // B row within k-tile
    const int bj = (tid & 15) * 4;    // B col offset
    const int tx = tid & 15;
    const int ty = tid >> 4;

    unsigned long long acc[2][4];
#pragma unroll
    for (int p = 0; p < 2; p++)
#pragma unroll
        for (int q = 0; q < 4; q++) acc[p][q] = 0ull;

    const bool nfull = ((nBase + BN) <= N) && ((N & 3) == 0);
    const float* Arow = A + (size_t)(mBase + am) * Ktot + k0 + ak;
    const int ntiles = Kc / TK;

    for (int t = 0; t < ntiles; t++) {
        // load A tile (transposed into shared)
        float4 av = *(const float4*)(Arow + t * TK);
        As[ak + 0][am] = av.x;
        As[ak + 1][am] = av.y;
        As[ak + 2][am] = av.z;
        As[ak + 3][am] = av.w;
        // load B tile
        int kk = k0 + t * TK + bk;
        int krow = PERM ? ((kk & 255) * 49 + (kk >> 8)) : kk;
        const float* Bp = B + (size_t)krow * N + nBase + bj;
        float4 bv;
        if (nfull) {
            bv = *(const float4*)Bp;
        } else {
            bv.x = (nBase + bj + 0 < N) ? Bp[0] : 0.0f;
            bv.y = (nBase + bj + 1 < N) ? Bp[1] : 0.0f;
            bv.z = (nBase + bj + 2 < N) ? Bp[2] : 0.0f;
            bv.w = (nBase + bj + 3 < N) ? Bp[3] : 0.0f;
        }
        *(float4*)&Bs[bk][bj] = bv;
        __syncthreads();

#pragma unroll
        for (int kx = 0; kx < TK; kx++) {
            ulonglong2 ap = *(const ulonglong2*)&As[kx][ty * 4];
            float4 bq = *(const float4*)&Bs[kx][tx * 4];
            unsigned long long b0 = dup_f(bq.x);
            unsigned long long b1 = dup_f(bq.y);
            unsigned long long b2 = dup_f(bq.z);
            unsigned long long b3 = dup_f(bq.w);
            fma2(acc[0][0], ap.x, b0);
            fma2(acc[0][1], ap.x, b1);
            fma2(acc[0][2], ap.x, b2);
            fma2(acc[0][3], ap.x, b3);
            fma2(acc[1][0], ap.y, b0);
            fma2(acc[1][1], ap.y, b1);
            fma2(acc[1][2], ap.y, b2);
            fma2(acc[1][3], ap.y, b3);
        }
        __syncthreads();
    }

    float* P = g_part + partOff + (size_t)split * NROIS * N;
#pragma unroll
    for (int p = 0; p < 2; p++) {
        int m = mBase + ty * 4 + p * 2;
#pragma unroll
        for (int q = 0; q < 4; q++) {
            float2 v = unpack2(acc[p][q]);
            int col = nBase + tx * 4 + q;
            if (col < N) {
                P[(size_t)m * N + col] = v.x;
                P[(size_t)(m + 1) * N + col] = v.y;
            }
        }
    }
}

// fixed-order split reduction + bias (+ optional relu)
__global__ void reduce_bias(const float* __restrict__ bias, int outSel, int N,
                            int splits, int relu, int partOff) {
    float* outs[4] = {g_h1, g_h2, g_cls, g_loc};
    float* out = outs[outSel];
    int idx = blockIdx.x * 256 + threadIdx.x;
    int MN = NROIS * N;
    if (idx >= MN) return;
    const float* P = g_part + partOff;
    float s = 0.0f;
    for (int sp = 0; sp < splits; sp++) s += P[(size_t)sp * MN + idx];
    s += bias[idx % N];
    if (relu) s = fmaxf(s, 0.0f);
    out[idx] = s;
}

// ---------------------------------------------------------------------------
// Per-roi postprocess: softmax, box decode, accumulate, argmax, roi update.
// ---------------------------------------------------------------------------
__global__ void postproc(int stage) {
    const int n = blockIdx.x;
    const int tid = threadIdx.x;   // 128 threads

    __shared__ float sl[81];
    __shared__ float ssc[80];
    __shared__ float sbox[80][4];
    __shared__ float sred[128];
    __shared__ int sidx[128];

    if (tid < 81) sl[tid] = g_cls[n * 81 + tid];
    __syncthreads();

    // max
    float m = -1e30f;
    if (tid < 81) m = sl[tid];
    sred[tid] = m;
    __syncthreads();
    for (int off = 64; off > 0; off >>= 1) {
        if (tid < off) sred[tid] = fmaxf(sred[tid], sred[tid + off]);
        __syncthreads();
    }
    const float M = sred[0];
    __syncthreads();

    // exp-sum
    float e = (tid < 81) ? expf(sl[tid] - M) : 0.0f;
    sred[tid] = e;
    __syncthreads();
    for (int off = 64; off > 0; off >>= 1) {
        if (tid < off) sred[tid] += sred[tid + off];
        __syncthreads();
    }
    const float S = sred[0];
    __syncthreads();
    if (tid >= 1 && tid < 81) ssc[tid - 1] = e / S;
    __syncthreads();

    const float r0 = g_roi[n * 4 + 0];
    const float r1 = g_roi[n * 4 + 1];
    const float r2 = g_roi[n * 4 + 2];
    const float r3 = g_roi[n * 4 + 3];
    const float chy = r2 - r0, chx = r3 - r1;
    const float cy = r0 + chy * 0.5f, cx = r1 + chx * 0.5f;
    const float4 stds = c_stds[stage];

    if (tid < 80) {
        const int j = tid;
        g_pres[n * 80 + j] += ssc[j];
        const float* lp = g_loc + n * 324 + (j + 1) * 4;
        float l0 = lp[0] * stds.x;
        float l1 = lp[1] * stds.y;
        float l2 = lp[2] * stds.z;
        float l3 = lp[3] * stds.w;
        float ty_ = l0 * chy + cy;
        float tx_ = l1 * chx + cx;
        float hy = expf(l2) * chy;
        float hx = expf(l3) * chx;
        float b0 = ty_ - hy * 0.5f;
        float b1 = tx_ - hx * 0.5f;
        float b2 = ty_ + hy * 0.5f;
        float b3 = tx_ + hx * 0.5f;
        sbox[j][0] = b0; sbox[j][1] = b1; sbox[j][2] = b2; sbox[j][3] = b3;
        float* pb = g_preb + (size_t)(n * 80 + j) * 4;
        pb[0] += b0; pb[1] += b1; pb[2] += b2; pb[3] += b3;
    }

    // argmax (first occurrence on ties)
    sred[tid] = (tid < 80) ? ssc[tid] : -1e30f;
    sidx[tid] = (tid < 80) ? tid : (1 << 30);
    __syncthreads();
    for (int off = 64; off > 0; off >>= 1) {
        if (tid < off) {
            float v2 = sred[tid + off];
            int i2 = sidx[tid + off];
            if (v2 > sred[tid] || (v2 == sred[tid] && i2 < sidx[tid])) {
                sred[tid] = v2;
                sidx[tid] = i2;
            }
        }
        __syncthreads();
    }
    if (tid == 0) {
        int best = sidx[0];
        float nr0 = fminf(fmaxf(sbox[best][0], 0.0f), 1024.0f);
        float nr1 = fminf(fmaxf(sbox[best][1], 0.0f), 1024.0f);
        float nr2 = fminf(fmaxf(sbox[best][2], 0.0f), 1024.0f);
        float nr3 = fminf(fmaxf(sbox[best][3], 0.0f), 1024.0f);
        g_roi[n * 4 + 0] = nr0;
        g_roi[n * 4 + 1] = nr1;
        g_roi[n * 4 + 2] = nr2;
        g_roi[n * 4 + 3] = nr3;
        if (stage < 2) {
            float hy = nr2 - nr0, hx = nr3 - nr1;
            if (!(hy >= 16.0f && hx >= 16.0f)) g_valid[n] = 0.0f;
        }
    }
}

// final: d_out = [pre_b/3*m (81920) | pre_s/3*m (20480)]
__global__ void finalize_kernel(float* __restrict__ out) {
    int idx = blockIdx.x * 256 + threadIdx.x;   // grid covers 81920
    if (idx < NROIS * NUM_CLS * 4) {
        int n = idx / (NUM_CLS * 4);
        out[idx] = g_preb[idx] * (1.0f / 3.0f) * g_valid[n];
    }
    if (idx < NROIS * NUM_CLS) {
        int n = idx / NUM_CLS;
        out[NROIS * NUM_CLS * 4 + idx] = g_pres[idx] * (1.0f / 3.0f) * g_valid[n];
    }
}

// ---------------------------------------------------------------------------
// launch
// ---------------------------------------------------------------------------
extern "C" void kernel_launch(void* const* d_in, const int* in_sizes, int n_in,
                              void* d_out, int out_size) {
    (void)in_sizes; (void)n_in; (void)out_size;
    const float* P0 = (const float*)d_in[0];
    const float* P1 = (const float*)d_in[1];
    const float* P2 = (const float*)d_in[2];
    const float* P3 = (const float*)d_in[3];
    const float* rois = (const float*)d_in[4];

    dim3 tb(32, 8);
    transpose_kernel<<<dim3(65536 / 32, 8), tb>>>(P0, 0, 65536);
    transpose_kernel<<<dim3(16384 / 32, 8), tb>>>(P1, 1, 16384);
    transpose_kernel<<<dim3(4096 / 32, 8), tb>>>(P2, 2, 4096);
    transpose_kernel<<<dim3(1024 / 32, 8), tb>>>(P3, 3, 1024);

    init_state<<<320, 256>>>(rois);

    const int LOC_PART_OFF = 4 * NROIS * 81;  // 82944 floats into g_part

    for (int s = 0; s < 3; s++) {
        const float* W1 = (const float*)d_in[5 + 8 * s + 0];
        const float* b1 = (const float*)d_in[5 + 8 * s + 1];
        const float* W2 = (const float*)d_in[5 + 8 * s + 2];
        const float* b2 = (const float*)d_in[5 + 8 * s + 3];
        const float* Wc = (const float*)d_in[5 + 8 * s + 4];
        const float* bc = (const float*)d_in[5 + 8 * s + 5];
        const float* Wl = (const float*)d_in[5 + 8 * s + 6];
        const float* bl = (const float*)d_in[5 + 8 * s + 7];

        roialign_kernel<<<NROIS, 256>>>();

        // FC1: [256,12544] x [12544,1024], split-K=8
        gemm_splitk<true><<<dim3(16, 4, 8), 256>>>(W1, 0, 1024, 12544, 1568, 0);
        reduce_bias<<<1024, 256>>>(b1, 0, 1024, 8, 1, 0);

        // FC2: [256,1024] x [1024,1024], split-K=4
        gemm_splitk<false><<<dim3(16, 4, 4), 256>>>(W2, 1, 1024, 1024, 256, 0);
        reduce_bias<<<1024, 256>>>(b2, 1, 1024, 4, 1, 0);

        // heads
        gemm_splitk<false><<<dim3(2, 4, 4), 256>>>(Wc, 2, 81, 1024, 256, 0);
        gemm_splitk<false><<<dim3(6, 4, 4), 256>>>(Wl, 2, 324, 1024, 256, LOC_PART_OFF);
        reduce_bias<<<81, 256>>>(bc, 2, 81, 4, 0, 0);
        reduce_bias<<<324, 256>>>(bl, 3, 324, 4, 0, LOC_PART_OFF);

        postproc<<<NROIS, 128>>>(s);
    }

    finalize_kernel<<<320, 256>>>((float*)d_out);
}